// round 1
// baseline (speedup 1.0000x reference)
#include <cuda_runtime.h>
#include <math.h>

#define NVW 4
#define B_ 4
#define N_ 256
#define C_ 768
#define H_ 12
#define HD_ 64
#define HID_ 3072
#define MROWS (B_*N_)   // 1024 rows per view

// ---------------- scratch (device globals; no allocation) ----------------
__device__ float g_Xn [NVW*MROWS*C_];
__device__ float g_qkv[NVW*MROWS*3*C_];
__device__ float g_ctx[NVW*MROWS*C_];
__device__ float g_x  [NVW*MROWS*C_];
__device__ float g_hn [NVW*MROWS*C_];
__device__ float g_h1 [NVW*MROWS*HID_];
__device__ float g_x2 [NVW*MROWS*C_];
__device__ float g_kv [NVW*MROWS*2*C_];
__device__ float g_qh [NVW*C_];
__device__ float g_c2 [NVW*B_*C_];

__device__ __forceinline__ float gelu_exact(float x) {
    return 0.5f * x * (1.0f + erff(x * 0.70710678118654752f));
}

// ---------------- LayerNorm ----------------
// remap=1: input is X[(b*NV+v), n, c], output row order [v][b][n].
// pervw=1: gamma/beta are per-view [NV][C].
__global__ __launch_bounds__(256) void ln_kernel(
    const float* __restrict__ X, const float* __restrict__ g,
    const float* __restrict__ be, float* __restrict__ Y,
    int remap, int pervw)
{
    int r = blockIdx.x;                 // output row in [0, NV*B*N)
    int v = r / (B_ * N_);
    long inrow;
    if (remap) {
        int rem = r % (B_ * N_);
        int bb = rem / N_;
        int n  = rem % N_;
        inrow = ((long)(bb * NVW + v) * N_ + n);
    } else {
        inrow = r;
    }
    const float* x = X + inrow * C_;
    float* y = Y + (long)r * C_;
    const float* gg = g  + (pervw ? v * C_ : 0);
    const float* bb2 = be + (pervw ? v * C_ : 0);

    int t = threadIdx.x;
    float v0 = x[t], v1 = x[t + 256], v2 = x[t + 512];
    float s  = v0 + v1 + v2;
    float sq = v0 * v0 + v1 * v1 + v2 * v2;

    __shared__ float rs[256], rq[256];
    rs[t] = s; rq[t] = sq;
    __syncthreads();
    for (int off = 128; off > 0; off >>= 1) {
        if (t < off) { rs[t] += rs[t + off]; rq[t] += rq[t + off]; }
        __syncthreads();
    }
    float mean = rs[0] * (1.0f / C_);
    float var  = rq[0] * (1.0f / C_) - mean * mean;
    float rstd = rsqrtf(var + 1e-6f);

    y[t]       = (v0 - mean) * rstd * gg[t]       + bb2[t];
    y[t + 256] = (v1 - mean) * rstd * gg[t + 256] + bb2[t + 256];
    y[t + 512] = (v2 - mean) * rstd * gg[t + 512] + bb2[t + 512];
}

// ---------------- Generic batched NT GEMM ----------------
// C[v][m][d] = epi( alpha*(sum_k A[v][m][k]*W[v][d][k] + bias[v][d]) ) + res[v][m][d]
// act: 0 = none, 1 = exact GELU
#define BM 64
#define BN 64
#define BK 16

__global__ __launch_bounds__(256) void gemm_nt(
    const float* __restrict__ A, const float* __restrict__ W,
    const float* __restrict__ bias, const float* __restrict__ res,
    float* __restrict__ Cout,
    int Kdim, int D,
    long strideA, long strideW, long strideBias, long strideRes, long strideC,
    float alpha, int act)
{
    int v = blockIdx.z;
    const float* Av = A + (long)v * strideA;
    const float* Wv = W + (long)v * strideW;
    float* Cv = Cout + (long)v * strideC;
    int bm = blockIdx.y * BM, bn = blockIdx.x * BN;

    __shared__ __align__(16) float As[BK][BM + 4];
    __shared__ __align__(16) float Ws[BK][BN + 4];

    int t = threadIdx.x;
    int tm = t >> 4, tn = t & 15;
    int lrow = t >> 2;
    int lc4  = (t & 3) * 4;

    float acc[4][4] = {};

    for (int k0 = 0; k0 < Kdim; k0 += BK) {
        float4 a4 = *(const float4*)(Av + (long)(bm + lrow) * Kdim + k0 + lc4);
        float4 w4 = *(const float4*)(Wv + (long)(bn + lrow) * Kdim + k0 + lc4);
        As[lc4 + 0][lrow] = a4.x; As[lc4 + 1][lrow] = a4.y;
        As[lc4 + 2][lrow] = a4.z; As[lc4 + 3][lrow] = a4.w;
        Ws[lc4 + 0][lrow] = w4.x; Ws[lc4 + 1][lrow] = w4.y;
        Ws[lc4 + 2][lrow] = w4.z; Ws[lc4 + 3][lrow] = w4.w;
        __syncthreads();
        #pragma unroll
        for (int kk = 0; kk < BK; kk++) {
            float4 af = *(const float4*)&As[kk][tm * 4];
            float4 wf = *(const float4*)&Ws[kk][tn * 4];
            float aa[4] = {af.x, af.y, af.z, af.w};
            float ww[4] = {wf.x, wf.y, wf.z, wf.w};
            #pragma unroll
            for (int i = 0; i < 4; i++)
                #pragma unroll
                for (int j = 0; j < 4; j++)
                    acc[i][j] += aa[i] * ww[j];
        }
        __syncthreads();
    }

    #pragma unroll
    for (int i = 0; i < 4; i++) {
        int row = bm + tm * 4 + i;
        int col = bn + tn * 4;
        float4 o4;
        float vals[4];
        #pragma unroll
        for (int j = 0; j < 4; j++) {
            float bv = bias ? bias[(long)v * strideBias + col + j] : 0.0f;
            float val = alpha * (acc[i][j] + bv);
            if (act == 1) val = gelu_exact(val);
            if (res) val += res[(long)v * strideRes + (long)row * D + col + j];
            vals[j] = val;
        }
        o4.x = vals[0]; o4.y = vals[1]; o4.z = vals[2]; o4.w = vals[3];
        *(float4*)&Cv[(long)row * D + col] = o4;
    }
}

// ---------------- Pairwise cross-view attention with mean over j ----------------
// block = (h, b, i); thread = query row n. Output ctx_mean[i][b][n][h*64+e].
__global__ __launch_bounds__(256) void attn_kernel(
    const float* __restrict__ qkv, float* __restrict__ ctx_out)
{
    int h = blockIdx.x, b = blockIdx.y, i = blockIdx.z;
    int n = threadIdx.x;
    const float scale = 0.125f;   // hd=64 -> 1/8

    __shared__ __align__(16) float sKV[64 * 64];

    // load q into registers
    float q[64];
    const float* qptr = qkv + ((long)((i * B_ + b) * N_ + n)) * (3 * C_) + h * HD_;
    #pragma unroll
    for (int e4 = 0; e4 < 16; e4++) {
        float4 t4 = *(const float4*)(qptr + e4 * 4);
        q[e4 * 4 + 0] = t4.x; q[e4 * 4 + 1] = t4.y;
        q[e4 * 4 + 2] = t4.z; q[e4 * 4 + 3] = t4.w;
    }

    float ctx[64];
    #pragma unroll
    for (int e = 0; e < 64; e++) ctx[e] = 0.0f;

    float sloc[256];   // per-thread scores (local memory)

    for (int j = 0; j < NVW; j++) {
        const float* kbase = qkv + ((long)((j * B_ + b) * N_)) * (3 * C_) + C_ + h * HD_;
        const float* vbase = kbase + C_;

        float smax = -1e30f;
        // score pass over 4 key chunks of 64
        for (int c = 0; c < 4; c++) {
            __syncthreads();
            #pragma unroll
            for (int r = 0; r < 4; r++) {
                int F = threadIdx.x + 256 * r;       // 0..1023 float4 slots
                int row  = F >> 4;
                int col4 = (F & 15) << 2;
                float4 t4 = *(const float4*)(kbase + (long)(c * 64 + row) * (3 * C_) + col4);
                *(float4*)&sKV[row * 64 + col4] = t4;
            }
            __syncthreads();
            for (int m = 0; m < 64; m++) {
                float d0 = 0.f, d1 = 0.f, d2 = 0.f, d3 = 0.f;
                const float* kr = &sKV[m * 64];
                #pragma unroll
                for (int e = 0; e < 64; e += 4) {
                    d0 += q[e + 0] * kr[e + 0];
                    d1 += q[e + 1] * kr[e + 1];
                    d2 += q[e + 2] * kr[e + 2];
                    d3 += q[e + 3] * kr[e + 3];
                }
                float s = ((d0 + d1) + (d2 + d3)) * scale;
                sloc[c * 64 + m] = s;
                smax = fmaxf(smax, s);
            }
        }
        // softmax exp + sum
        float ssum = 0.0f;
        for (int m = 0; m < 256; m++) {
            float e_ = __expf(sloc[m] - smax);
            sloc[m] = e_;
            ssum += e_;
        }
        float inv = 1.0f / ssum;

        // ctx pass over 4 value chunks
        for (int c = 0; c < 4; c++) {
            __syncthreads();
            #pragma unroll
            for (int r = 0; r < 4; r++) {
                int F = threadIdx.x + 256 * r;
                int row  = F >> 4;
                int col4 = (F & 15) << 2;
                float4 t4 = *(const float4*)(vbase + (long)(c * 64 + row) * (3 * C_) + col4);
                *(float4*)&sKV[row * 64 + col4] = t4;
            }
            __syncthreads();
            for (int m = 0; m < 64; m++) {
                float pm = sloc[c * 64 + m] * inv;
                const float* vr = &sKV[m * 64];
                #pragma unroll
                for (int e = 0; e < 64; e++) ctx[e] += pm * vr[e];
            }
        }
    }

    // mean over j (x0.25), write out
    float* outp = ctx_out + ((long)((i * B_ + b) * N_ + n)) * C_ + h * HD_;
    #pragma unroll
    for (int e4 = 0; e4 < 16; e4++) {
        float4 o4;
        o4.x = ctx[e4 * 4 + 0] * 0.25f;
        o4.y = ctx[e4 * 4 + 1] * 0.25f;
        o4.z = ctx[e4 * 4 + 2] * 0.25f;
        o4.w = ctx[e4 * 4 + 3] * 0.25f;
        *(float4*)(outp + e4 * 4) = o4;
    }
}

// ---------------- learnable-query projection: qh[v][d] ----------------
__global__ __launch_bounds__(256) void qh_kernel(
    const float* __restrict__ query, const float* __restrict__ w,
    const float* __restrict__ bq, float* __restrict__ qh)
{
    int v = blockIdx.x;
    int t = threadIdx.x;
    for (int d = t; d < C_; d += 256) {
        const float* wr = w + (long)v * (3 * C_) * C_ + (long)d * C_;  // wq rows [0,C)
        float acc = 0.0f;
        #pragma unroll 4
        for (int c = 0; c < C_; c++) acc += query[c] * wr[c];
        qh[v * C_ + d] = acc + bq[(long)v * (3 * C_) + d];
    }
}

// ---------------- cross attention (single query) -> c2[v][b][C] ----------------
__global__ __launch_bounds__(256) void cross_attn_kernel(
    const float* __restrict__ kv, const float* __restrict__ qh,
    float* __restrict__ c2)
{
    int h = blockIdx.x, b = blockIdx.y, v = blockIdx.z;
    int t = threadIdx.x;   // key index n

    __shared__ float p[256];
    __shared__ float red[256];
    __shared__ float part[4][64];

    const float* kvb = kv + ((long)(v * B_ + b) * N_) * (2 * C_);
    const float* qhp = qh + v * C_ + h * HD_;
    const float* krow = kvb + (long)t * (2 * C_) + h * HD_;

    float s = 0.0f;
    #pragma unroll
    for (int e = 0; e < 64; e++) s += qhp[e] * krow[e];
    s *= 0.125f;

    red[t] = s; __syncthreads();
    for (int off = 128; off > 0; off >>= 1) {
        if (t < off) red[t] = fmaxf(red[t], red[t + off]);
        __syncthreads();
    }
    float mx = red[0];
    __syncthreads();

    float e_ = __expf(s - mx);
    p[t] = e_; red[t] = e_;
    __syncthreads();
    for (int off = 128; off > 0; off >>= 1) {
        if (t < off) red[t] += red[t + off];
        __syncthreads();
    }
    float inv = 1.0f / red[0];
    __syncthreads();

    int e = t & 63, pid = t >> 6;
    float acc = 0.0f;
    for (int n = pid * 64; n < pid * 64 + 64; n++)
        acc += p[n] * kvb[(long)n * (2 * C_) + C_ + h * HD_ + e];
    part[pid][e] = acc;
    __syncthreads();
    if (t < 64) {
        float r = (part[0][t] + part[1][t]) + (part[2][t] + part[3][t]);
        c2[(long)(v * B_ + b) * C_ + h * HD_ + t] = r * inv;
    }
}

// ---------------- output projection + broadcast over N ----------------
__global__ __launch_bounds__(256) void out_kernel(
    const float* __restrict__ c2, const float* __restrict__ w,
    const float* __restrict__ bias, float* __restrict__ out)
{
    int v = blockIdx.x, b = blockIdx.y;
    int t = threadIdx.x;

    __shared__ float sc[C_];
    for (int c = t; c < C_; c += 256) sc[c] = c2[(long)(v * B_ + b) * C_ + c];
    __syncthreads();

    float o[3];
    #pragma unroll
    for (int r = 0; r < 3; r++) {
        int co = t + r * 256;
        const float* wr = w + (long)v * C_ * C_ + (long)co * C_;
        float d0 = 0.f, d1 = 0.f, d2 = 0.f, d3 = 0.f;
        #pragma unroll 4
        for (int c = 0; c < C_; c += 4) {
            d0 += sc[c + 0] * wr[c + 0];
            d1 += sc[c + 1] * wr[c + 1];
            d2 += sc[c + 2] * wr[c + 2];
            d3 += sc[c + 3] * wr[c + 3];
        }
        o[r] = ((d0 + d1) + (d2 + d3)) + bias[v * C_ + co];
    }
    for (int n = 0; n < N_; n++) {
        long base = ((long)b * N_ + n) * (NVW * C_) + (long)v * C_;
        #pragma unroll
        for (int r = 0; r < 3; r++) out[base + t + r * 256] = o[r];
    }
}

// ---------------- launch ----------------
extern "C" void kernel_launch(void* const* d_in, const int* in_sizes, int n_in,
                              void* d_out, int out_size)
{
    const float* X        = (const float*)d_in[0];
    const float* norm1_g  = (const float*)d_in[1];
    const float* norm1_b  = (const float*)d_in[2];
    const float* qkv_w    = (const float*)d_in[3];
    const float* proj_w   = (const float*)d_in[4];
    const float* proj_b   = (const float*)d_in[5];
    const float* norm2_g  = (const float*)d_in[6];
    const float* norm2_b  = (const float*)d_in[7];
    const float* fc1_w    = (const float*)d_in[8];
    const float* fc1_b    = (const float*)d_in[9];
    const float* fc2_w    = (const float*)d_in[10];
    const float* fc2_b    = (const float*)d_in[11];
    const float* query    = (const float*)d_in[12];
    const float* mha_in_w = (const float*)d_in[13];
    const float* mha_in_b = (const float*)d_in[14];
    const float* mha_out_w= (const float*)d_in[15];
    const float* mha_out_b= (const float*)d_in[16];
    float* out = (float*)d_out;

    float *Xn, *qkvb, *ctx, *x, *hn, *h1, *x2, *kv, *qh, *c2;
    cudaGetSymbolAddress((void**)&Xn,   g_Xn);
    cudaGetSymbolAddress((void**)&qkvb, g_qkv);
    cudaGetSymbolAddress((void**)&ctx,  g_ctx);
    cudaGetSymbolAddress((void**)&x,    g_x);
    cudaGetSymbolAddress((void**)&hn,   g_hn);
    cudaGetSymbolAddress((void**)&h1,   g_h1);
    cudaGetSymbolAddress((void**)&x2,   g_x2);
    cudaGetSymbolAddress((void**)&kv,   g_kv);
    cudaGetSymbolAddress((void**)&qh,   g_qh);
    cudaGetSymbolAddress((void**)&c2,   g_c2);

    const long MC  = (long)MROWS * C_;
    const long MH  = (long)MROWS * HID_;

    // 1. LN1 (remap [b*NV+v] -> [v][b]), shared params
    ln_kernel<<<NVW * B_ * N_, 256>>>(X, norm1_g, norm1_b, Xn, 1, 0);

    // 2. QKV GEMM: [1024,768] x [2304,768]^T -> [1024,2304], no bias
    gemm_nt<<<dim3(3 * C_ / BN, MROWS / BM, NVW), 256>>>(
        Xn, qkv_w, nullptr, nullptr, qkvb,
        C_, 3 * C_, MC, (long)3 * C_ * C_, 0, 0, (long)MROWS * 3 * C_, 1.0f, 0);

    // 3. pairwise attention, mean over j
    attn_kernel<<<dim3(H_, B_, NVW), 256>>>(qkvb, ctx);

    // 4. proj GEMM, alpha=2 folds the residual doubling: x = 2*(ctx@W^T + b)
    gemm_nt<<<dim3(C_ / BN, MROWS / BM, NVW), 256>>>(
        ctx, proj_w, proj_b, nullptr, x,
        C_, C_, MC, (long)C_ * C_, C_, 0, MC, 2.0f, 0);

    // 5. LN2 (per-view params)
    ln_kernel<<<NVW * B_ * N_, 256>>>(x, norm2_g, norm2_b, hn, 0, 1);

    // 6. fc1 GEMM + bias + GELU
    gemm_nt<<<dim3(HID_ / BN, MROWS / BM, NVW), 256>>>(
        hn, fc1_w, fc1_b, nullptr, h1,
        C_, HID_, MC, (long)HID_ * C_, HID_, 0, MH, 1.0f, 1);

    // 7. fc2 GEMM + bias + residual add (x)
    gemm_nt<<<dim3(C_ / BN, MROWS / BM, NVW), 256>>>(
        h1, fc2_w, fc2_b, x, x2,
        HID_, C_, MH, (long)C_ * HID_, C_, MC, MC, 1.0f, 0);

    // 8. learnable query projection
    qh_kernel<<<NVW, 256>>>(query, mha_in_w, mha_in_b, qh);

    // 9. K/V projection of x2: W rows [C, 3C) of mha_in_w -> [1024, 1536]
    gemm_nt<<<dim3(2 * C_ / BN, MROWS / BM, NVW), 256>>>(
        x2, mha_in_w + (long)C_ * C_, mha_in_b + C_, nullptr, kv,
        C_, 2 * C_, MC, (long)3 * C_ * C_, (long)3 * C_, 0, (long)MROWS * 2 * C_, 1.0f, 0);

    // 10. single-query cross attention -> c2[v][b][C]
    cross_attn_kernel<<<dim3(H_, B_, NVW), 256>>>(kv, qh, c2);

    // 11. output projection + broadcast over N
    out_kernel<<<dim3(NVW, B_), 256>>>(c2, mha_out_w, mha_out_b, out);
}

// round 2
// speedup vs baseline: 1.0036x; 1.0036x over previous
#include <cuda_runtime.h>
#include <math.h>

#define NVW 4
#define B_ 4
#define N_ 256
#define C_ 768
#define H_ 12
#define HD_ 64
#define HID_ 3072
#define MROWS (B_*N_)   // 1024 rows per view

// ---------------- scratch (device globals; no allocation) ----------------
__device__ float g_Xn [NVW*MROWS*C_];
__device__ float g_qkv[NVW*MROWS*3*C_];
__device__ float g_ctx[NVW*MROWS*C_];
__device__ float g_x  [NVW*MROWS*C_];
__device__ float g_hn [NVW*MROWS*C_];
__device__ float g_h1 [NVW*MROWS*HID_];
__device__ float g_x2 [NVW*MROWS*C_];
__device__ float g_kv [NVW*MROWS*2*C_];
__device__ float g_qh [NVW*C_];
__device__ float g_c2 [NVW*B_*C_];

__device__ __forceinline__ float gelu_exact(float x) {
    return 0.5f * x * (1.0f + erff(x * 0.70710678118654752f));
}

// ---------------- LayerNorm ----------------
// remap=1: input is X[(b*NV+v), n, c], output row order [v][b][n].
// pervw=1: gamma/beta are per-view [NV][C].
__global__ __launch_bounds__(256) void ln_kernel(
    const float* __restrict__ X, const float* __restrict__ g,
    const float* __restrict__ be, float* __restrict__ Y,
    int remap, int pervw)
{
    int r = blockIdx.x;                 // output row in [0, NV*B*N)
    int v = r / (B_ * N_);
    long inrow;
    if (remap) {
        int rem = r % (B_ * N_);
        int bb = rem / N_;
        int n  = rem % N_;
        inrow = ((long)(bb * NVW + v) * N_ + n);
    } else {
        inrow = r;
    }
    const float* x = X + inrow * C_;
    float* y = Y + (long)r * C_;
    const float* gg = g  + (pervw ? v * C_ : 0);
    const float* bb2 = be + (pervw ? v * C_ : 0);

    int t = threadIdx.x;
    float v0 = x[t], v1 = x[t + 256], v2 = x[t + 512];
    float s  = v0 + v1 + v2;
    float sq = v0 * v0 + v1 * v1 + v2 * v2;

    __shared__ float rs[256], rq[256];
    rs[t] = s; rq[t] = sq;
    __syncthreads();
    for (int off = 128; off > 0; off >>= 1) {
        if (t < off) { rs[t] += rs[t + off]; rq[t] += rq[t + off]; }
        __syncthreads();
    }
    float mean = rs[0] * (1.0f / C_);
    float var  = rq[0] * (1.0f / C_) - mean * mean;
    float rstd = rsqrtf(var + 1e-6f);

    y[t]       = (v0 - mean) * rstd * gg[t]       + bb2[t];
    y[t + 256] = (v1 - mean) * rstd * gg[t + 256] + bb2[t + 256];
    y[t + 512] = (v2 - mean) * rstd * gg[t + 512] + bb2[t + 512];
}

// ---------------- Generic batched NT GEMM ----------------
// C[v][m][d] = epi( alpha*(sum_k A[v][m][k]*W[v][d][k] + bias[v][d]) ) + res[v][m][d]
// act: 0 = none, 1 = exact GELU
#define BM 64
#define BN 64
#define BK 16

__global__ __launch_bounds__(256) void gemm_nt(
    const float* __restrict__ A, const float* __restrict__ W,
    const float* __restrict__ bias, const float* __restrict__ res,
    float* __restrict__ Cout,
    int Kdim, int D,
    long strideA, long strideW, long strideBias, long strideRes, long strideC,
    float alpha, int act)
{
    int v = blockIdx.z;
    const float* Av = A + (long)v * strideA;
    const float* Wv = W + (long)v * strideW;
    float* Cv = Cout + (long)v * strideC;
    int bm = blockIdx.y * BM, bn = blockIdx.x * BN;

    __shared__ __align__(16) float As[BK][BM + 4];
    __shared__ __align__(16) float Ws[BK][BN + 4];

    int t = threadIdx.x;
    int tm = t >> 4, tn = t & 15;
    int lrow = t >> 2;
    int lc4  = (t & 3) * 4;

    float acc[4][4] = {};

    for (int k0 = 0; k0 < Kdim; k0 += BK) {
        float4 a4 = *(const float4*)(Av + (long)(bm + lrow) * Kdim + k0 + lc4);
        float4 w4 = *(const float4*)(Wv + (long)(bn + lrow) * Kdim + k0 + lc4);
        As[lc4 + 0][lrow] = a4.x; As[lc4 + 1][lrow] = a4.y;
        As[lc4 + 2][lrow] = a4.z; As[lc4 + 3][lrow] = a4.w;
        Ws[lc4 + 0][lrow] = w4.x; Ws[lc4 + 1][lrow] = w4.y;
        Ws[lc4 + 2][lrow] = w4.z; Ws[lc4 + 3][lrow] = w4.w;
        __syncthreads();
        #pragma unroll
        for (int kk = 0; kk < BK; kk++) {
            float4 af = *(const float4*)&As[kk][tm * 4];
            float4 wf = *(const float4*)&Ws[kk][tn * 4];
            float aa[4] = {af.x, af.y, af.z, af.w};
            float ww[4] = {wf.x, wf.y, wf.z, wf.w};
            #pragma unroll
            for (int i = 0; i < 4; i++)
                #pragma unroll
                for (int j = 0; j < 4; j++)
                    acc[i][j] += aa[i] * ww[j];
        }
        __syncthreads();
    }

    #pragma unroll
    for (int i = 0; i < 4; i++) {
        int row = bm + tm * 4 + i;
        int col = bn + tn * 4;
        float4 o4;
        float vals[4];
        #pragma unroll
        for (int j = 0; j < 4; j++) {
            float bv = bias ? bias[(long)v * strideBias + col + j] : 0.0f;
            float val = alpha * (acc[i][j] + bv);
            if (act == 1) val = gelu_exact(val);
            if (res) val += res[(long)v * strideRes + (long)row * D + col + j];
            vals[j] = val;
        }
        o4.x = vals[0]; o4.y = vals[1]; o4.z = vals[2]; o4.w = vals[3];
        *(float4*)&Cv[(long)row * D + col] = o4;
    }
}

// ---------------- Pairwise cross-view attention with mean over j ----------------
// block = (h, b, i); thread = query row n. Output ctx_mean[i][b][n][h*64+e].
__global__ __launch_bounds__(256) void attn_kernel(
    const float* __restrict__ qkv, float* __restrict__ ctx_out)
{
    int h = blockIdx.x, b = blockIdx.y, i = blockIdx.z;
    int n = threadIdx.x;
    const float scale = 0.125f;   // hd=64 -> 1/8

    __shared__ __align__(16) float sKV[64 * 64];

    // load q into registers
    float q[64];
    const float* qptr = qkv + ((long)((i * B_ + b) * N_ + n)) * (3 * C_) + h * HD_;
    #pragma unroll
    for (int e4 = 0; e4 < 16; e4++) {
        float4 t4 = *(const float4*)(qptr + e4 * 4);
        q[e4 * 4 + 0] = t4.x; q[e4 * 4 + 1] = t4.y;
        q[e4 * 4 + 2] = t4.z; q[e4 * 4 + 3] = t4.w;
    }

    float ctx[64];
    #pragma unroll
    for (int e = 0; e < 64; e++) ctx[e] = 0.0f;

    float sloc[256];   // per-thread scores (local memory)

    for (int j = 0; j < NVW; j++) {
        const float* kbase = qkv + ((long)((j * B_ + b) * N_)) * (3 * C_) + C_ + h * HD_;
        const float* vbase = kbase + C_;

        float smax = -1e30f;
        // score pass over 4 key chunks of 64
        for (int c = 0; c < 4; c++) {
            __syncthreads();
            #pragma unroll
            for (int r = 0; r < 4; r++) {
                int F = threadIdx.x + 256 * r;       // 0..1023 float4 slots
                int row  = F >> 4;
                int col4 = (F & 15) << 2;
                float4 t4 = *(const float4*)(kbase + (long)(c * 64 + row) * (3 * C_) + col4);
                *(float4*)&sKV[row * 64 + col4] = t4;
            }
            __syncthreads();
            for (int m = 0; m < 64; m++) {
                float d0 = 0.f, d1 = 0.f, d2 = 0.f, d3 = 0.f;
                const float* kr = &sKV[m * 64];
                #pragma unroll
                for (int e = 0; e < 64; e += 4) {
                    d0 += q[e + 0] * kr[e + 0];
                    d1 += q[e + 1] * kr[e + 1];
                    d2 += q[e + 2] * kr[e + 2];
                    d3 += q[e + 3] * kr[e + 3];
                }
                float s = ((d0 + d1) + (d2 + d3)) * scale;
                sloc[c * 64 + m] = s;
                smax = fmaxf(smax, s);
            }
        }
        // softmax exp + sum
        float ssum = 0.0f;
        for (int m = 0; m < 256; m++) {
            float e_ = __expf(sloc[m] - smax);
            sloc[m] = e_;
            ssum += e_;
        }
        float inv = 1.0f / ssum;

        // ctx pass over 4 value chunks
        for (int c = 0; c < 4; c++) {
            __syncthreads();
            #pragma unroll
            for (int r = 0; r < 4; r++) {
                int F = threadIdx.x + 256 * r;
                int row  = F >> 4;
                int col4 = (F & 15) << 2;
                float4 t4 = *(const float4*)(vbase + (long)(c * 64 + row) * (3 * C_) + col4);
                *(float4*)&sKV[row * 64 + col4] = t4;
            }
            __syncthreads();
            for (int m = 0; m < 64; m++) {
                float pm = sloc[c * 64 + m] * inv;
                const float* vr = &sKV[m * 64];
                #pragma unroll
                for (int e = 0; e < 64; e++) ctx[e] += pm * vr[e];
            }
        }
    }

    // mean over j (x0.25), write out
    float* outp = ctx_out + ((long)((i * B_ + b) * N_ + n)) * C_ + h * HD_;
    #pragma unroll
    for (int e4 = 0; e4 < 16; e4++) {
        float4 o4;
        o4.x = ctx[e4 * 4 + 0] * 0.25f;
        o4.y = ctx[e4 * 4 + 1] * 0.25f;
        o4.z = ctx[e4 * 4 + 2] * 0.25f;
        o4.w = ctx[e4 * 4 + 3] * 0.25f;
        *(float4*)(outp + e4 * 4) = o4;
    }
}

// ---------------- learnable-query projection: qh[v][d] ----------------
__global__ __launch_bounds__(256) void qh_kernel(
    const float* __restrict__ query, const float* __restrict__ w,
    const float* __restrict__ bq, float* __restrict__ qh)
{
    int v = blockIdx.x;
    int t = threadIdx.x;
    for (int d = t; d < C_; d += 256) {
        const float* wr = w + (long)v * (3 * C_) * C_ + (long)d * C_;  // wq rows [0,C)
        float acc = 0.0f;
        #pragma unroll 4
        for (int c = 0; c < C_; c++) acc += query[c] * wr[c];
        qh[v * C_ + d] = acc + bq[(long)v * (3 * C_) + d];
    }
}

// ---------------- cross attention (single query) -> c2[v][b][C] ----------------
__global__ __launch_bounds__(256) void cross_attn_kernel(
    const float* __restrict__ kv, const float* __restrict__ qh,
    float* __restrict__ c2)
{
    int h = blockIdx.x, b = blockIdx.y, v = blockIdx.z;
    int t = threadIdx.x;   // key index n

    __shared__ float p[256];
    __shared__ float red[256];
    __shared__ float part[4][64];

    const float* kvb = kv + ((long)(v * B_ + b) * N_) * (2 * C_);
    const float* qhp = qh + v * C_ + h * HD_;
    const float* krow = kvb + (long)t * (2 * C_) + h * HD_;

    float s = 0.0f;
    #pragma unroll
    for (int e = 0; e < 64; e++) s += qhp[e] * krow[e];
    s *= 0.125f;

    red[t] = s; __syncthreads();
    for (int off = 128; off > 0; off >>= 1) {
        if (t < off) red[t] = fmaxf(red[t], red[t + off]);
        __syncthreads();
    }
    float mx = red[0];
    __syncthreads();

    float e_ = __expf(s - mx);
    p[t] = e_; red[t] = e_;
    __syncthreads();
    for (int off = 128; off > 0; off >>= 1) {
        if (t < off) red[t] += red[t + off];
        __syncthreads();
    }
    float inv = 1.0f / red[0];
    __syncthreads();

    int e = t & 63, pid = t >> 6;
    float acc = 0.0f;
    for (int n = pid * 64; n < pid * 64 + 64; n++)
        acc += p[n] * kvb[(long)n * (2 * C_) + C_ + h * HD_ + e];
    part[pid][e] = acc;
    __syncthreads();
    if (t < 64) {
        float r = (part[0][t] + part[1][t]) + (part[2][t] + part[3][t]);
        c2[(long)(v * B_ + b) * C_ + h * HD_ + t] = r * inv;
    }
}

// ---------------- output projection + broadcast over N ----------------
__global__ __launch_bounds__(256) void out_kernel(
    const float* __restrict__ c2, const float* __restrict__ w,
    const float* __restrict__ bias, float* __restrict__ out)
{
    int v = blockIdx.x, b = blockIdx.y;
    int t = threadIdx.x;

    __shared__ float sc[C_];
    for (int c = t; c < C_; c += 256) sc[c] = c2[(long)(v * B_ + b) * C_ + c];
    __syncthreads();

    float o[3];
    #pragma unroll
    for (int r = 0; r < 3; r++) {
        int co = t + r * 256;
        const float* wr = w + (long)v * C_ * C_ + (long)co * C_;
        float d0 = 0.f, d1 = 0.f, d2 = 0.f, d3 = 0.f;
        #pragma unroll 4
        for (int c = 0; c < C_; c += 4) {
            d0 += sc[c + 0] * wr[c + 0];
            d1 += sc[c + 1] * wr[c + 1];
            d2 += sc[c + 2] * wr[c + 2];
            d3 += sc[c + 3] * wr[c + 3];
        }
        o[r] = ((d0 + d1) + (d2 + d3)) + bias[v * C_ + co];
    }
    for (int n = 0; n < N_; n++) {
        long base = ((long)b * N_ + n) * (NVW * C_) + (long)v * C_;
        #pragma unroll
        for (int r = 0; r < 3; r++) out[base + t + r * 256] = o[r];
    }
}

// ---------------- launch ----------------
extern "C" void kernel_launch(void* const* d_in, const int* in_sizes, int n_in,
                              void* d_out, int out_size)
{
    const float* X        = (const float*)d_in[0];
    const float* norm1_g  = (const float*)d_in[1];
    const float* norm1_b  = (const float*)d_in[2];
    const float* qkv_w    = (const float*)d_in[3];
    const float* proj_w   = (const float*)d_in[4];
    const float* proj_b   = (const float*)d_in[5];
    const float* norm2_g  = (const float*)d_in[6];
    const float* norm2_b  = (const float*)d_in[7];
    const float* fc1_w    = (const float*)d_in[8];
    const float* fc1_b    = (const float*)d_in[9];
    const float* fc2_w    = (const float*)d_in[10];
    const float* fc2_b    = (const float*)d_in[11];
    const float* query    = (const float*)d_in[12];
    const float* mha_in_w = (const float*)d_in[13];
    const float* mha_in_b = (const float*)d_in[14];
    const float* mha_out_w= (const float*)d_in[15];
    const float* mha_out_b= (const float*)d_in[16];
    float* out = (float*)d_out;

    float *Xn, *qkvb, *ctx, *x, *hn, *h1, *x2, *kv, *qh, *c2;
    cudaGetSymbolAddress((void**)&Xn,   g_Xn);
    cudaGetSymbolAddress((void**)&qkvb, g_qkv);
    cudaGetSymbolAddress((void**)&ctx,  g_ctx);
    cudaGetSymbolAddress((void**)&x,    g_x);
    cudaGetSymbolAddress((void**)&hn,   g_hn);
    cudaGetSymbolAddress((void**)&h1,   g_h1);
    cudaGetSymbolAddress((void**)&x2,   g_x2);
    cudaGetSymbolAddress((void**)&kv,   g_kv);
    cudaGetSymbolAddress((void**)&qh,   g_qh);
    cudaGetSymbolAddress((void**)&c2,   g_c2);

    const long MC  = (long)MROWS * C_;
    const long MH  = (long)MROWS * HID_;

    // 1. LN1 (remap [b*NV+v] -> [v][b]), shared params
    ln_kernel<<<NVW * B_ * N_, 256>>>(X, norm1_g, norm1_b, Xn, 1, 0);

    // 2. QKV GEMM: [1024,768] x [2304,768]^T -> [1024,2304], no bias
    gemm_nt<<<dim3(3 * C_ / BN, MROWS / BM, NVW), 256>>>(
        Xn, qkv_w, nullptr, nullptr, qkvb,
        C_, 3 * C_, MC, (long)3 * C_ * C_, 0, 0, (long)MROWS * 3 * C_, 1.0f, 0);

    // 3. pairwise attention, mean over j
    attn_kernel<<<dim3(H_, B_, NVW), 256>>>(qkvb, ctx);

    // 4. proj GEMM, alpha=2 folds the residual doubling: x = 2*(ctx@W^T + b)
    gemm_nt<<<dim3(C_ / BN, MROWS / BM, NVW), 256>>>(
        ctx, proj_w, proj_b, nullptr, x,
        C_, C_, MC, (long)C_ * C_, C_, 0, MC, 2.0f, 0);

    // 5. LN2 (per-view params)
    ln_kernel<<<NVW * B_ * N_, 256>>>(x, norm2_g, norm2_b, hn, 0, 1);

    // 6. fc1 GEMM + bias + GELU
    gemm_nt<<<dim3(HID_ / BN, MROWS / BM, NVW), 256>>>(
        hn, fc1_w, fc1_b, nullptr, h1,
        C_, HID_, MC, (long)HID_ * C_, HID_, 0, MH, 1.0f, 1);

    // 7. fc2 GEMM + bias + residual add (x)
    gemm_nt<<<dim3(C_ / BN, MROWS / BM, NVW), 256>>>(
        h1, fc2_w, fc2_b, x, x2,
        HID_, C_, MH, (long)C_ * HID_, C_, MC, MC, 1.0f, 0);

    // 8. learnable query projection
    qh_kernel<<<NVW, 256>>>(query, mha_in_w, mha_in_b, qh);

    // 9. K/V projection of x2: W rows [C, 3C) of mha_in_w -> [1024, 1536]
    gemm_nt<<<dim3(2 * C_ / BN, MROWS / BM, NVW), 256>>>(
        x2, mha_in_w + (long)C_ * C_, mha_in_b + C_, nullptr, kv,
        C_, 2 * C_, MC, (long)3 * C_ * C_, (long)3 * C_, 0, (long)MROWS * 2 * C_, 1.0f, 0);

    // 10. single-query cross attention -> c2[v][b][C]
    cross_attn_kernel<<<dim3(H_, B_, NVW), 256>>>(kv, qh, c2);

    // 11. output projection + broadcast over N
    out_kernel<<<dim3(NVW, B_), 256>>>(c2, mha_out_w, mha_out_b, out);
}

// round 3
// speedup vs baseline: 1.1250x; 1.1210x over previous
#include <cuda_runtime.h>
#include <math.h>

#define NVW 4
#define B_ 4
#define N_ 256
#define C_ 768
#define H_ 12
#define HD_ 64
#define HID_ 3072
#define MROWS (B_*N_)   // 1024 rows per view

// ---------------- scratch (device globals; no allocation) ----------------
__device__ float g_Xn [NVW*MROWS*C_];
__device__ float g_qkv[NVW*MROWS*3*C_];
__device__ float g_ctx[NVW*MROWS*C_];
__device__ float g_x  [NVW*MROWS*C_];
__device__ float g_hn [NVW*MROWS*C_];
__device__ float g_h1 [NVW*MROWS*HID_];
__device__ float g_x2 [NVW*MROWS*C_];
__device__ float g_kv [NVW*MROWS*2*C_];
__device__ float g_qh [NVW*C_];
__device__ float g_c2 [NVW*B_*C_];

__device__ __forceinline__ float gelu_exact(float x) {
    return 0.5f * x * (1.0f + erff(x * 0.70710678118654752f));
}

// ---------------- LayerNorm ----------------
__global__ __launch_bounds__(256) void ln_kernel(
    const float* __restrict__ X, const float* __restrict__ g,
    const float* __restrict__ be, float* __restrict__ Y,
    int remap, int pervw)
{
    int r = blockIdx.x;
    int v = r / (B_ * N_);
    long inrow;
    if (remap) {
        int rem = r % (B_ * N_);
        int bb = rem / N_;
        int n  = rem % N_;
        inrow = ((long)(bb * NVW + v) * N_ + n);
    } else {
        inrow = r;
    }
    const float* x = X + inrow * C_;
    float* y = Y + (long)r * C_;
    const float* gg = g  + (pervw ? v * C_ : 0);
    const float* bb2 = be + (pervw ? v * C_ : 0);

    int t = threadIdx.x;
    float v0 = x[t], v1 = x[t + 256], v2 = x[t + 512];
    float s  = v0 + v1 + v2;
    float sq = v0 * v0 + v1 * v1 + v2 * v2;

    __shared__ float rs[256], rq[256];
    rs[t] = s; rq[t] = sq;
    __syncthreads();
    for (int off = 128; off > 0; off >>= 1) {
        if (t < off) { rs[t] += rs[t + off]; rq[t] += rq[t + off]; }
        __syncthreads();
    }
    float mean = rs[0] * (1.0f / C_);
    float var  = rq[0] * (1.0f / C_) - mean * mean;
    float rstd = rsqrtf(var + 1e-6f);

    y[t]       = (v0 - mean) * rstd * gg[t]       + bb2[t];
    y[t + 256] = (v1 - mean) * rstd * gg[t + 256] + bb2[t + 256];
    y[t + 512] = (v2 - mean) * rstd * gg[t + 512] + bb2[t + 512];
}

// ---------------- Generic batched NT GEMM, 128x128x16, 8x8 microtile ----------------
// C[v][m][d] = epi( alpha*(acc + bias[v][d]) ) (+ res[v][m][d])
#define TBM 128
#define TBN 128
#define TBK 16
#define SPAD 4

__global__ __launch_bounds__(256, 2) void gemm_nt(
    const float* __restrict__ A, const float* __restrict__ W,
    const float* __restrict__ bias, const float* __restrict__ res,
    float* __restrict__ Cout,
    int Kdim, int D,
    long strideA, long strideW, long strideBias, long strideRes, long strideC,
    float alpha, int act)
{
    int v = blockIdx.z;
    const float* Av = A + (long)v * strideA;
    const float* Wv = W + (long)v * strideW;
    float* Cv = Cout + (long)v * strideC;
    int bm = blockIdx.y * TBM, bn = blockIdx.x * TBN;

    __shared__ __align__(16) float As[2][TBK][TBM + SPAD];
    __shared__ __align__(16) float Ws[2][TBK][TBN + SPAD];

    int t = threadIdx.x;
    int tm = t >> 4;   // 0..15 -> row groups tm*4 and 64+tm*4
    int tn = t & 15;   // 0..15 -> col groups tn*4 and 64+tn*4

    // staging: idx in [0,512): row = idx>>2, c4 = (idx&3)*4
    int r0 = t >> 2;            // rows for idx=t
    int c40 = (t & 3) << 2;
    int r1 = (t + 256) >> 2;    // rows for idx=t+256
    int c41 = c40;              // (idx&3) identical since 256 % 4 == 0

    float acc[8][8] = {};
    float4 aR[2], wR[2];

    int steps = Kdim / TBK;

    // preload tile 0
    aR[0] = *(const float4*)(Av + (long)(bm + r0) * Kdim + c40);
    aR[1] = *(const float4*)(Av + (long)(bm + r1) * Kdim + c41);
    wR[0] = *(const float4*)(Wv + (long)(bn + r0) * Kdim + c40);
    wR[1] = *(const float4*)(Wv + (long)(bn + r1) * Kdim + c41);

    int buf = 0;
    {
        As[buf][c40 + 0][r0] = aR[0].x; As[buf][c40 + 1][r0] = aR[0].y;
        As[buf][c40 + 2][r0] = aR[0].z; As[buf][c40 + 3][r0] = aR[0].w;
        As[buf][c41 + 0][r1] = aR[1].x; As[buf][c41 + 1][r1] = aR[1].y;
        As[buf][c41 + 2][r1] = aR[1].z; As[buf][c41 + 3][r1] = aR[1].w;
        Ws[buf][c40 + 0][r0] = wR[0].x; Ws[buf][c40 + 1][r0] = wR[0].y;
        Ws[buf][c40 + 2][r0] = wR[0].z; Ws[buf][c40 + 3][r0] = wR[0].w;
        Ws[buf][c41 + 0][r1] = wR[1].x; Ws[buf][c41 + 1][r1] = wR[1].y;
        Ws[buf][c41 + 2][r1] = wR[1].z; Ws[buf][c41 + 3][r1] = wR[1].w;
    }
    __syncthreads();

    for (int s = 0; s < steps; s++) {
        int kn = (s + 1) * TBK;
        bool more = (s + 1 < steps);
        if (more) {
            aR[0] = *(const float4*)(Av + (long)(bm + r0) * Kdim + kn + c40);
            aR[1] = *(const float4*)(Av + (long)(bm + r1) * Kdim + kn + c41);
            wR[0] = *(const float4*)(Wv + (long)(bn + r0) * Kdim + kn + c40);
            wR[1] = *(const float4*)(Wv + (long)(bn + r1) * Kdim + kn + c41);
        }

        #pragma unroll
        for (int kk = 0; kk < TBK; kk++) {
            float4 a0 = *(const float4*)&As[buf][kk][tm * 4];
            float4 a1 = *(const float4*)&As[buf][kk][64 + tm * 4];
            float4 w0 = *(const float4*)&Ws[buf][kk][tn * 4];
            float4 w1 = *(const float4*)&Ws[buf][kk][64 + tn * 4];
            float a[8] = {a0.x, a0.y, a0.z, a0.w, a1.x, a1.y, a1.z, a1.w};
            float w[8] = {w0.x, w0.y, w0.z, w0.w, w1.x, w1.y, w1.z, w1.w};
            #pragma unroll
            for (int i = 0; i < 8; i++)
                #pragma unroll
                for (int j = 0; j < 8; j++)
                    acc[i][j] += a[i] * w[j];
        }

        if (more) {
            int nb = buf ^ 1;
            As[nb][c40 + 0][r0] = aR[0].x; As[nb][c40 + 1][r0] = aR[0].y;
            As[nb][c40 + 2][r0] = aR[0].z; As[nb][c40 + 3][r0] = aR[0].w;
            As[nb][c41 + 0][r1] = aR[1].x; As[nb][c41 + 1][r1] = aR[1].y;
            As[nb][c41 + 2][r1] = aR[1].z; As[nb][c41 + 3][r1] = aR[1].w;
            Ws[nb][c40 + 0][r0] = wR[0].x; Ws[nb][c40 + 1][r0] = wR[0].y;
            Ws[nb][c40 + 2][r0] = wR[0].z; Ws[nb][c40 + 3][r0] = wR[0].w;
            Ws[nb][c41 + 0][r1] = wR[1].x; Ws[nb][c41 + 1][r1] = wR[1].y;
            Ws[nb][c41 + 2][r1] = wR[1].z; Ws[nb][c41 + 3][r1] = wR[1].w;
            __syncthreads();
            buf = nb;
        }
    }

    // epilogue
    #pragma unroll
    for (int i = 0; i < 8; i++) {
        int row = bm + ((i < 4) ? (tm * 4 + i) : (64 + tm * 4 + i - 4));
        #pragma unroll
        for (int jj = 0; jj < 2; jj++) {
            int col = bn + jj * 64 + tn * 4;
            float vals[4];
            #pragma unroll
            for (int j = 0; j < 4; j++) {
                float bv = bias ? bias[(long)v * strideBias + col + j] : 0.0f;
                float val = alpha * (acc[i][jj * 4 + j] + bv);
                if (act == 1) val = gelu_exact(val);
                if (res) val += res[(long)v * strideRes + (long)row * D + col + j];
                vals[j] = val;
            }
            float4 o4 = {vals[0], vals[1], vals[2], vals[3]};
            *(float4*)&Cv[(long)row * D + col] = o4;
        }
    }
}

// ---------------- Pairwise cross-view attention with mean over j ----------------
__global__ __launch_bounds__(256) void attn_kernel(
    const float* __restrict__ qkv, float* __restrict__ ctx_out)
{
    int h = blockIdx.x, b = blockIdx.y, i = blockIdx.z;
    int n = threadIdx.x;
    const float scale = 0.125f;

    __shared__ __align__(16) float sKV[64 * 64];

    float q[64];
    const float* qptr = qkv + ((long)((i * B_ + b) * N_ + n)) * (3 * C_) + h * HD_;
    #pragma unroll
    for (int e4 = 0; e4 < 16; e4++) {
        float4 t4 = *(const float4*)(qptr + e4 * 4);
        q[e4 * 4 + 0] = t4.x; q[e4 * 4 + 1] = t4.y;
        q[e4 * 4 + 2] = t4.z; q[e4 * 4 + 3] = t4.w;
    }

    float ctx[64];
    #pragma unroll
    for (int e = 0; e < 64; e++) ctx[e] = 0.0f;

    float sloc[256];

    for (int j = 0; j < NVW; j++) {
        const float* kbase = qkv + ((long)((j * B_ + b) * N_)) * (3 * C_) + C_ + h * HD_;
        const float* vbase = kbase + C_;

        float smax = -1e30f;
        for (int c = 0; c < 4; c++) {
            __syncthreads();
            #pragma unroll
            for (int r = 0; r < 4; r++) {
                int F = threadIdx.x + 256 * r;
                int row  = F >> 4;
                int col4 = (F & 15) << 2;
                float4 t4 = *(const float4*)(kbase + (long)(c * 64 + row) * (3 * C_) + col4);
                *(float4*)&sKV[row * 64 + col4] = t4;
            }
            __syncthreads();
            for (int m = 0; m < 64; m++) {
                float d0 = 0.f, d1 = 0.f, d2 = 0.f, d3 = 0.f;
                const float* kr = &sKV[m * 64];
                #pragma unroll
                for (int e = 0; e < 64; e += 4) {
                    d0 += q[e + 0] * kr[e + 0];
                    d1 += q[e + 1] * kr[e + 1];
                    d2 += q[e + 2] * kr[e + 2];
                    d3 += q[e + 3] * kr[e + 3];
                }
                float s = ((d0 + d1) + (d2 + d3)) * scale;
                sloc[c * 64 + m] = s;
                smax = fmaxf(smax, s);
            }
        }
        float ssum = 0.0f;
        for (int m = 0; m < 256; m++) {
            float e_ = __expf(sloc[m] - smax);
            sloc[m] = e_;
            ssum += e_;
        }
        float inv = 1.0f / ssum;

        for (int c = 0; c < 4; c++) {
            __syncthreads();
            #pragma unroll
            for (int r = 0; r < 4; r++) {
                int F = threadIdx.x + 256 * r;
                int row  = F >> 4;
                int col4 = (F & 15) << 2;
                float4 t4 = *(const float4*)(vbase + (long)(c * 64 + row) * (3 * C_) + col4);
                *(float4*)&sKV[row * 64 + col4] = t4;
            }
            __syncthreads();
            for (int m = 0; m < 64; m++) {
                float pm = sloc[c * 64 + m] * inv;
                const float* vr = &sKV[m * 64];
                #pragma unroll
                for (int e = 0; e < 64; e++) ctx[e] += pm * vr[e];
            }
        }
    }

    float* outp = ctx_out + ((long)((i * B_ + b) * N_ + n)) * C_ + h * HD_;
    #pragma unroll
    for (int e4 = 0; e4 < 16; e4++) {
        float4 o4;
        o4.x = ctx[e4 * 4 + 0] * 0.25f;
        o4.y = ctx[e4 * 4 + 1] * 0.25f;
        o4.z = ctx[e4 * 4 + 2] * 0.25f;
        o4.w = ctx[e4 * 4 + 3] * 0.25f;
        *(float4*)(outp + e4 * 4) = o4;
    }
}

// ---------------- learnable-query projection ----------------
__global__ __launch_bounds__(256) void qh_kernel(
    const float* __restrict__ query, const float* __restrict__ w,
    const float* __restrict__ bq, float* __restrict__ qh)
{
    int v = blockIdx.x;
    int t = threadIdx.x;
    for (int d = t; d < C_; d += 256) {
        const float* wr = w + (long)v * (3 * C_) * C_ + (long)d * C_;
        float acc = 0.0f;
        #pragma unroll 4
        for (int c = 0; c < C_; c++) acc += query[c] * wr[c];
        qh[v * C_ + d] = acc + bq[(long)v * (3 * C_) + d];
    }
}

// ---------------- cross attention (single query) ----------------
__global__ __launch_bounds__(256) void cross_attn_kernel(
    const float* __restrict__ kv, const float* __restrict__ qh,
    float* __restrict__ c2)
{
    int h = blockIdx.x, b = blockIdx.y, v = blockIdx.z;
    int t = threadIdx.x;

    __shared__ float p[256];
    __shared__ float red[256];
    __shared__ float part[4][64];

    const float* kvb = kv + ((long)(v * B_ + b) * N_) * (2 * C_);
    const float* qhp = qh + v * C_ + h * HD_;
    const float* krow = kvb + (long)t * (2 * C_) + h * HD_;

    float s = 0.0f;
    #pragma unroll
    for (int e = 0; e < 64; e++) s += qhp[e] * krow[e];
    s *= 0.125f;

    red[t] = s; __syncthreads();
    for (int off = 128; off > 0; off >>= 1) {
        if (t < off) red[t] = fmaxf(red[t], red[t + off]);
        __syncthreads();
    }
    float mx = red[0];
    __syncthreads();

    float e_ = __expf(s - mx);
    p[t] = e_; red[t] = e_;
    __syncthreads();
    for (int off = 128; off > 0; off >>= 1) {
        if (t < off) red[t] += red[t + off];
        __syncthreads();
    }
    float inv = 1.0f / red[0];
    __syncthreads();

    int e = t & 63, pid = t >> 6;
    float acc = 0.0f;
    for (int n = pid * 64; n < pid * 64 + 64; n++)
        acc += p[n] * kvb[(long)n * (2 * C_) + C_ + h * HD_ + e];
    part[pid][e] = acc;
    __syncthreads();
    if (t < 64) {
        float r = (part[0][t] + part[1][t]) + (part[2][t] + part[3][t]);
        c2[(long)(v * B_ + b) * C_ + h * HD_ + t] = r * inv;
    }
}

// ---------------- output projection + broadcast over N ----------------
__global__ __launch_bounds__(256) void out_kernel(
    const float* __restrict__ c2, const float* __restrict__ w,
    const float* __restrict__ bias, float* __restrict__ out)
{
    int v = blockIdx.x, b = blockIdx.y;
    int t = threadIdx.x;

    __shared__ float sc[C_];
    for (int c = t; c < C_; c += 256) sc[c] = c2[(long)(v * B_ + b) * C_ + c];
    __syncthreads();

    float o[3];
    #pragma unroll
    for (int r = 0; r < 3; r++) {
        int co = t + r * 256;
        const float* wr = w + (long)v * C_ * C_ + (long)co * C_;
        float d0 = 0.f, d1 = 0.f, d2 = 0.f, d3 = 0.f;
        #pragma unroll 4
        for (int c = 0; c < C_; c += 4) {
            d0 += sc[c + 0] * wr[c + 0];
            d1 += sc[c + 1] * wr[c + 1];
            d2 += sc[c + 2] * wr[c + 2];
            d3 += sc[c + 3] * wr[c + 3];
        }
        o[r] = ((d0 + d1) + (d2 + d3)) + bias[v * C_ + co];
    }
    for (int n = 0; n < N_; n++) {
        long base = ((long)b * N_ + n) * (NVW * C_) + (long)v * C_;
        #pragma unroll
        for (int r = 0; r < 3; r++) out[base + t + r * 256] = o[r];
    }
}

// ---------------- launch ----------------
extern "C" void kernel_launch(void* const* d_in, const int* in_sizes, int n_in,
                              void* d_out, int out_size)
{
    const float* X        = (const float*)d_in[0];
    const float* norm1_g  = (const float*)d_in[1];
    const float* norm1_b  = (const float*)d_in[2];
    const float* qkv_w    = (const float*)d_in[3];
    const float* proj_w   = (const float*)d_in[4];
    const float* proj_b   = (const float*)d_in[5];
    const float* norm2_g  = (const float*)d_in[6];
    const float* norm2_b  = (const float*)d_in[7];
    const float* fc1_w    = (const float*)d_in[8];
    const float* fc1_b    = (const float*)d_in[9];
    const float* fc2_w    = (const float*)d_in[10];
    const float* fc2_b    = (const float*)d_in[11];
    const float* query    = (const float*)d_in[12];
    const float* mha_in_w = (const float*)d_in[13];
    const float* mha_in_b = (const float*)d_in[14];
    const float* mha_out_w= (const float*)d_in[15];
    const float* mha_out_b= (const float*)d_in[16];
    float* out = (float*)d_out;

    float *Xn, *qkvb, *ctx, *x, *hn, *h1, *x2, *kv, *qh, *c2;
    cudaGetSymbolAddress((void**)&Xn,   g_Xn);
    cudaGetSymbolAddress((void**)&qkvb, g_qkv);
    cudaGetSymbolAddress((void**)&ctx,  g_ctx);
    cudaGetSymbolAddress((void**)&x,    g_x);
    cudaGetSymbolAddress((void**)&hn,   g_hn);
    cudaGetSymbolAddress((void**)&h1,   g_h1);
    cudaGetSymbolAddress((void**)&x2,   g_x2);
    cudaGetSymbolAddress((void**)&kv,   g_kv);
    cudaGetSymbolAddress((void**)&qh,   g_qh);
    cudaGetSymbolAddress((void**)&c2,   g_c2);

    const long MC  = (long)MROWS * C_;
    const long MH  = (long)MROWS * HID_;

    // 1. LN1 (remap [b*NV+v] -> [v][b]), shared params
    ln_kernel<<<NVW * B_ * N_, 256>>>(X, norm1_g, norm1_b, Xn, 1, 0);

    // 2. QKV GEMM: [1024,768] x [2304,768]^T -> [1024,2304]
    gemm_nt<<<dim3(3 * C_ / TBN, MROWS / TBM, NVW), 256>>>(
        Xn, qkv_w, nullptr, nullptr, qkvb,
        C_, 3 * C_, MC, (long)3 * C_ * C_, 0, 0, (long)MROWS * 3 * C_, 1.0f, 0);

    // 3. pairwise attention, mean over j
    attn_kernel<<<dim3(H_, B_, NVW), 256>>>(qkvb, ctx);

    // 4. proj GEMM, alpha=2 folds the residual doubling
    gemm_nt<<<dim3(C_ / TBN, MROWS / TBM, NVW), 256>>>(
        ctx, proj_w, proj_b, nullptr, x,
        C_, C_, MC, (long)C_ * C_, C_, 0, MC, 2.0f, 0);

    // 5. LN2 (per-view params)
    ln_kernel<<<NVW * B_ * N_, 256>>>(x, norm2_g, norm2_b, hn, 0, 1);

    // 6. fc1 GEMM + bias + GELU
    gemm_nt<<<dim3(HID_ / TBN, MROWS / TBM, NVW), 256>>>(
        hn, fc1_w, fc1_b, nullptr, h1,
        C_, HID_, MC, (long)HID_ * C_, HID_, 0, MH, 1.0f, 1);

    // 7. fc2 GEMM + bias + residual add (x)
    gemm_nt<<<dim3(C_ / TBN, MROWS / TBM, NVW), 256>>>(
        h1, fc2_w, fc2_b, x, x2,
        HID_, C_, MH, (long)C_ * HID_, C_, MC, MC, 1.0f, 0);

    // 8. learnable query projection
    qh_kernel<<<NVW, 256>>>(query, mha_in_w, mha_in_b, qh);

    // 9. K/V projection of x2
    gemm_nt<<<dim3(2 * C_ / TBN, MROWS / TBM, NVW), 256>>>(
        x2, mha_in_w + (long)C_ * C_, mha_in_b + C_, nullptr, kv,
        C_, 2 * C_, MC, (long)3 * C_ * C_, (long)3 * C_, 0, (long)MROWS * 2 * C_, 1.0f, 0);

    // 10. single-query cross attention -> c2[v][b][C]
    cross_attn_kernel<<<dim3(H_, B_, NVW), 256>>>(kv, qh, c2);

    // 11. output projection + broadcast over N
    out_kernel<<<dim3(NVW, B_), 256>>>(c2, mha_out_w, mha_out_b, out);
}